// round 10
// baseline (speedup 1.0000x reference)
#include <cuda_runtime.h>
#include <cstdint>

#define BS_ROWS     1024                      // B*S
#define VOCAB       50257
#define DMODEL      768
#define D4          (DMODEL / 4)              // 192 float4 per row
#define TOTAL_ELEMS (BS_ROWS * (long long)VOCAB)   // 51,463,168
#define NSEG        4
#define SEGLEN      12565                     // ceil(VOCAB/4); 4*12565 >= 50257
#define NTHREADS    128
#define CHUNK_F4    (NTHREADS * 4)            // 512 f4 = 8 KB per chunk

// Per-row "found" flag; cleared by prologue kernel each launch.
__device__ int g_found[BS_ROWS];

__global__ void clear_flags_kernel()
{
    g_found[threadIdx.x] = 0;                 // 1024 threads
}

// ---------------------------------------------------------------------------
// 4 blocks per row, each scanning one quarter-row segment. The finder
// publishes g_found[row]; sibling segments poll it each chunk and abort.
// ---------------------------------------------------------------------------
__global__ void __launch_bounds__(NTHREADS, 16)
seg_scan_embed_kernel(const uint4* __restrict__ oh4,
                      const float4* __restrict__ w4,
                      float4* __restrict__ out4)
{
    __shared__ int   s_found;
    __shared__ int   s_abort;
    __shared__ int   s_col;
    __shared__ float s_val;

    const unsigned row = blockIdx.x >> 2;
    const unsigned seg = blockIdx.x & 3u;
    const int      t   = threadIdx.x;

    if (t == 0) { s_found = 0; s_abort = 0; }
    __syncthreads();

    // Element range of this segment, covering aligned f4 range.
    const unsigned rowbeg = row * (unsigned)VOCAB;
    const unsigned rowend = rowbeg + (unsigned)VOCAB;
    const unsigned ebeg   = rowbeg + seg * (unsigned)SEGLEN;
    unsigned eend         = ebeg + (unsigned)SEGLEN;
    if (eend > rowend) eend = rowend;
    const unsigned s4 = ebeg >> 2;
    const unsigned e4 = (eend + 3u) >> 2;

    for (unsigned base = s4; base < e4; base += CHUNK_F4) {
        const unsigned i0 = base + (unsigned)t;

        uint4 v[4];
        #pragma unroll
        for (int u = 0; u < 4; u++) {
            unsigned idx = i0 + u * (unsigned)NTHREADS;
            v[u] = (idx < e4) ? __ldcs(&oh4[idx]) : make_uint4(0, 0, 0, 0);
        }

        // rare path: claim the nonzero only if it lies in MY element range
        #pragma unroll
        for (int u = 0; u < 4; u++) {
            if (v[u].x | v[u].y | v[u].z | v[u].w) {
                unsigned gb = (i0 + u * (unsigned)NTHREADS) * 4u;
                float f[4] = { __uint_as_float(v[u].x), __uint_as_float(v[u].y),
                               __uint_as_float(v[u].z), __uint_as_float(v[u].w) };
                #pragma unroll
                for (int k = 0; k < 4; k++) {
                    unsigned g = gb + k;
                    if (f[k] != 0.0f && g >= ebeg && g < eend) {
                        s_col   = (int)(g - rowbeg);
                        s_val   = f[k];
                        s_found = 1;
                    }
                }
            }
        }

        // poll sibling flag (L2-coherent read, bypass L1)
        if (t == 0) s_abort = __ldcg(&g_found[row]);
        __syncthreads();

        if (s_found) {
            if (t == 0) atomicExch(&g_found[row], 1);   // tell siblings ASAP
            break;
        }
        if (s_abort) break;                             // row solved elsewhere
        __syncthreads();                                // protect s_abort rewrite
    }

    // ---- emit (only the finder block): out[row,:] = v * weight[col,:] ----
    if (s_found) {
        const int   col = s_col;
        const float vv  = s_val;
        {
            float4 w = __ldg(&w4[(unsigned)col * D4 + t]);
            w.x *= vv; w.y *= vv; w.z *= vv; w.w *= vv;
            out4[row * D4 + t] = w;
        }
        if (t < D4 - NTHREADS) {                        // t < 64
            int j = t + NTHREADS;
            float4 w = __ldg(&w4[(unsigned)col * D4 + j]);
            w.x *= vv; w.y *= vv; w.z *= vv; w.w *= vv;
            out4[row * D4 + j] = w;
        }
    }
}

// ---------------------------------------------------------------------------
extern "C" void kernel_launch(void* const* d_in, const int* in_sizes, int n_in,
                              void* d_out, int out_size)
{
    const float* one_hot = nullptr;
    const float* weight  = nullptr;
    for (int i = 0; i < n_in; i++) {
        if (in_sizes[i] == (int)TOTAL_ELEMS)     one_hot = (const float*)d_in[i];
        else if (in_sizes[i] == VOCAB * DMODEL)  weight  = (const float*)d_in[i];
    }

    clear_flags_kernel<<<1, BS_ROWS>>>();
    seg_scan_embed_kernel<<<BS_ROWS * NSEG, NTHREADS>>>((const uint4*)one_hot,
                                                        (const float4*)weight,
                                                        (float4*)d_out);
}

// round 11
// speedup vs baseline: 1.1238x; 1.1238x over previous
#include <cuda_runtime.h>
#include <cstdint>

#define BS_ROWS     1024                      // B*S (power of two: item decode is shift/mask)
#define VOCAB       50257
#define DMODEL      768
#define D4          (DMODEL / 4)              // 192 float4 per row
#define TOTAL_ELEMS (BS_ROWS * (long long)VOCAB)
#define NTHREADS    256
#define NBLOCKS     1184                      // 148 SMs x 8 blocks = one wave
#define CHUNK_F4    (NTHREADS * 4)            // 1024 f4 = 16 KB
#define MAXC        13                        // ceil(ceil(VOCAB/4)/CHUNK_F4)
#define NITEMS      (MAXC * BS_ROWS)          // 13312 work items

__device__ int      g_found[BS_ROWS];
__device__ unsigned g_qhead;

__global__ void clear_kernel()
{
    g_found[threadIdx.x] = 0;                 // 1024 threads
    if (threadIdx.x == 0) g_qhead = 0;
}

// ---------------------------------------------------------------------------
// Breadth-first chunked scan: items ordered chunk-major so chunk 0 of every
// row is scanned before chunk 1 of any row. A solved row's remaining items
// are skipped via g_found.
// ---------------------------------------------------------------------------
__global__ void __launch_bounds__(NTHREADS, 8)
queue_scan_embed_kernel(const uint4* __restrict__ oh4,
                        const float4* __restrict__ w4,
                        float4* __restrict__ out4)
{
    __shared__ unsigned s_item;
    __shared__ int      s_skip;
    __shared__ int      s_found;
    __shared__ int      s_col;
    __shared__ float    s_val;

    const int t = threadIdx.x;

    for (;;) {
        // ---- pop one work item ----
        if (t == 0) {
            unsigned it = atomicAdd(&g_qhead, 1u);
            s_item = it;
            s_skip = (it < NITEMS) ? __ldcg(&g_found[it & (BS_ROWS - 1u)]) : 0;
            s_found = 0;
        }
        __syncthreads();
        const unsigned item = s_item;
        if (item >= NITEMS) break;
        if (s_skip) { __syncthreads(); continue; }     // row already solved

        const unsigned row = item & (BS_ROWS - 1u);
        const unsigned c   = item >> 10;               // chunk index

        // element / f4 ranges
        const unsigned rowbeg = row * (unsigned)VOCAB;
        const unsigned rowend = rowbeg + (unsigned)VOCAB;
        const unsigned s4     = rowbeg >> 2;
        const unsigned e4     = (rowend + 3u) >> 2;
        const unsigned base   = s4 + c * (unsigned)CHUNK_F4;
        const unsigned i0     = base + (unsigned)t;

        uint4 v[4];
        #pragma unroll
        for (int u = 0; u < 4; u++) {
            unsigned idx = i0 + u * (unsigned)NTHREADS;
            v[u] = (idx < e4) ? __ldcs(&oh4[idx]) : make_uint4(0, 0, 0, 0);
        }

        #pragma unroll
        for (int u = 0; u < 4; u++) {
            if (v[u].x | v[u].y | v[u].z | v[u].w) {   // rare
                unsigned gb = (i0 + u * (unsigned)NTHREADS) * 4u;
                float f[4] = { __uint_as_float(v[u].x), __uint_as_float(v[u].y),
                               __uint_as_float(v[u].z), __uint_as_float(v[u].w) };
                #pragma unroll
                for (int k = 0; k < 4; k++) {
                    unsigned g = gb + k;
                    if (f[k] != 0.0f && g >= rowbeg && g < rowend) {
                        s_col   = (int)(g - rowbeg);
                        s_val   = f[k];
                        s_found = 1;
                    }
                }
            }
        }
        __syncthreads();

        // ---- solver path: mark row done, emit output ----
        if (s_found) {
            if (t == 0) atomicExch(&g_found[row], 1);
            const int   col = s_col;
            const float vv  = s_val;
            if (t < D4) {
                float4 w = __ldg(&w4[(unsigned)col * D4 + t]);
                w.x *= vv; w.y *= vv; w.z *= vv; w.w *= vv;
                out4[row * D4 + t] = w;
            }
        }
        __syncthreads();                               // protect shared reuse
    }
}

// ---------------------------------------------------------------------------
extern "C" void kernel_launch(void* const* d_in, const int* in_sizes, int n_in,
                              void* d_out, int out_size)
{
    const float* one_hot = nullptr;
    const float* weight  = nullptr;
    for (int i = 0; i < n_in; i++) {
        if (in_sizes[i] == (int)TOTAL_ELEMS)     one_hot = (const float*)d_in[i];
        else if (in_sizes[i] == VOCAB * DMODEL)  weight  = (const float*)d_in[i];
    }

    clear_kernel<<<1, BS_ROWS>>>();
    queue_scan_embed_kernel<<<NBLOCKS, NTHREADS>>>((const uint4*)one_hot,
                                                   (const float4*)weight,
                                                   (float4*)d_out);
}